// round 14
// baseline (speedup 1.0000x reference)
#include <cuda_runtime.h>
#include <cuda_fp16.h>
#include <cstdint>

#define DI __device__ __forceinline__

static const int QL  = 128;
static const int VL  = 2048;
static const int HID = 1024;

// ---------------------------------------------------------------------------
// Scratch (device globals; no runtime allocation allowed). fp16 operands.
// ---------------------------------------------------------------------------
__device__ uint16_t s_q_h[4194304], s_q_l[4194304];     // split q (2-pass A)
__device__ uint16_t s_Wq_h[1048576];                    // Wq hi
__device__ uint16_t s_Wv_h[1048576];                    // Wv hi
__device__ uint16_t g_qh_h[4194304];                    // qp result [n][q][d]
__device__ uint16_t g_vh_h[67108864];                   // vp result [n][v][d]
__device__ uint16_t g_eh[67108864];                     // score e-values fp16 [n][q][v]
__device__ float g_A0[128], g_A1[128], g_A2[128], g_Cc[128];
__device__ float g_mp[524288], g_lp[524288];            // softmax partials [n][16][128]

// ---------------------------------------------------------------------------
DI uint32_t smem_u32(const void* p) {
    uint32_t a;
    asm("{ .reg .u64 t; cvta.to.shared.u64 t, %1; cvt.u32.u64 %0, t; }" : "=r"(a) : "l"(p));
    return a;
}

DI uint32_t sp2h(float a, float b, uint32_t& lo) {
    __half2 h = __floats2half2_rn(a, b);
    float2 f = __half22float2(h);
    __half2 l = __floats2half2_rn(a - f.x, b - f.y);
    lo = *(uint32_t*)&l;
    return *(uint32_t*)&h;
}
DI uint32_t pk2h(float a, float b) {
    __half2 h = __floats2half2_rn(a, b);
    return *(uint32_t*)&h;
}
DI float2 up2h(uint32_t v) {
    return __half22float2(*(__half2*)&v);
}

DI void ldm4(uint32_t* r, uint32_t a) {
    asm volatile("ldmatrix.sync.aligned.m8n8.x4.shared.b16 {%0,%1,%2,%3}, [%4];"
        : "=r"(r[0]), "=r"(r[1]), "=r"(r[2]), "=r"(r[3]) : "r"(a));
}
DI void ldm4t(uint32_t* r, uint32_t a) {
    asm volatile("ldmatrix.sync.aligned.m8n8.x4.trans.shared.b16 {%0,%1,%2,%3}, [%4];"
        : "=r"(r[0]), "=r"(r[1]), "=r"(r[2]), "=r"(r[3]) : "r"(a));
}

DI void mma16816(float* d, const uint32_t* a, uint32_t b0, uint32_t b1) {
    asm volatile("mma.sync.aligned.m16n8k16.row.col.f32.f16.f16.f32 "
        "{%0,%1,%2,%3},{%4,%5,%6,%7},{%8,%9},{%0,%1,%2,%3};"
        : "+f"(d[0]), "+f"(d[1]), "+f"(d[2]), "+f"(d[3])
        : "r"(a[0]), "r"(a[1]), "r"(a[2]), "r"(a[3]), "r"(b0), "r"(b1));
}

DI void cp16(uint32_t dst, const void* src) {
    asm volatile("cp.async.cg.shared.global [%0], [%1], 16;" :: "r"(dst), "l"(src));
}
DI void cp8(uint32_t dst, const void* src) {
    asm volatile("cp.async.ca.shared.global [%0], [%1], 8;" :: "r"(dst), "l"(src));
}
#define CP_COMMIT() asm volatile("cp.async.commit_group;" ::: "memory")
#define CP_WAIT2()  asm volatile("cp.async.wait_group 2;"  ::: "memory")

static const int TILE_B = 10240;
static const int BT3    = 8704;          // MODE 3 B tile: 32 rows x 272B
static const int A32_B  = 17408;         // MODE 1 fp32 A tile: 128 rows x 136B

// ---------------------------------------------------------------------------
// Unified GEMM, 128x128 tile, 3-stage pipeline, 2 CTAs/SM.
// MODE 0: qp = q@Wq^T + bq       -> g_qh_h       grid(8, 32)  cp.async A, 2-pass
// MODE 1: vp = v@Wv^T + bias+loc -> g_vh_h       grid(8, 512) cp.async fp32 A + smem cvt
// MODE 2: score: e=exp(s-m_tile) -> g_eh + (m,l) grid(16,256) cp.async A, 1-pass
// MODE 3: out = P@vh, P=e*corr   -> out; attn=P  grid(256)    reg A fp16; B trans
// ---------------------------------------------------------------------------
template <int MODE>
__global__ void __launch_bounds__(256, 2)
mma_gemm(const float* __restrict__ Ain, const float* __restrict__ biasv,
         const float* __restrict__ la, float* __restrict__ dsto)
{
    extern __shared__ char sm[];
    const uint32_t smb = smem_u32(sm);
    const int t = threadIdx.x, lane = t & 31, w = t >> 5;
    const int wm0 = (w & 3) * 32, wn0 = (w >> 2) * 64;

    constexpr int  K    = (MODE < 2) ? HID : (MODE == 2 ? 128 : VL);
    constexpr int  NC   = K / 32;
    constexpr int  NPA  = (MODE == 0) ? 2 : 1;
    constexpr int  BUF  = (MODE == 0) ? 3 * TILE_B
                        : (MODE == 1) ? (A32_B + 2 * TILE_B)
                        : (MODE == 2) ? 2 * TILE_B
                        :               (TILE_B + BT3);
    constexpr uint32_t AOFF = (MODE == 1) ? (uint32_t)A32_B : 0u;  // fp16 A tile
    constexpr uint32_t BOFF = (MODE == 0) ? 2u * TILE_B
                            : (MODE == 1) ? (uint32_t)(A32_B + TILE_B)
                            :               (uint32_t)TILE_B;
    constexpr bool REGA = (MODE == 3);

    const uint16_t *Ah = nullptr, *Al = nullptr, *Bh = nullptr;
    const uint16_t* Ae = nullptr;
    const float* Afp32 = nullptr;
    float* attw = nullptr;
    const float* mpRow = nullptr;
    float m_st = 0.f, li_st = 0.f;
    if (MODE == 0) {
        size_t ao = (size_t)blockIdx.y * 128 * HID, bo = (size_t)blockIdx.x * 128 * HID;
        Ah = s_q_h + ao; Al = s_q_l + ao; Bh = s_Wq_h + bo;
    } else if (MODE == 1) {
        Afp32 = Ain + (size_t)blockIdx.y * 128 * HID;
        Bh = s_Wv_h + (size_t)blockIdx.x * 128 * HID;
    } else if (MODE == 2) {
        Ah = g_qh_h + (size_t)blockIdx.y * QL * 128;
        Bh = g_vh_h + (size_t)blockIdx.y * VL * 128 + (size_t)blockIdx.x * 128 * 128;
    } else {
        Ae   = g_eh + (size_t)blockIdx.x * QL * VL;
        attw = dsto + 4194304 + (size_t)blockIdx.x * QL * VL;   // attn region
        Bh   = g_vh_h + (size_t)blockIdx.x * VL * 128;
        const int myrow = t >> 1;
        mpRow = g_mp + (size_t)blockIdx.x * 2048 + myrow;
        const float* lp = g_lp + (size_t)blockIdx.x * 2048 + myrow;
        float m = -1e30f;
#pragma unroll
        for (int i = 0; i < 16; i++) m = fmaxf(m, mpRow[i * 128]);
        float l = 0.f;
#pragma unroll
        for (int i = 0; i < 16; i++) l += lp[i * 128] * __expf(mpRow[i * 128] - m);
        m_st = m; li_st = 1.0f / l;
    }

    float acc[2][8][4];
#pragma unroll
    for (int i = 0; i < 2; i++)
#pragma unroll
        for (int j = 0; j < 8; j++)
#pragma unroll
            for (int k = 0; k < 4; k++) acc[i][j][k] = 0.f;

    // ---- cp.async loaders ----
    auto cp_chunk = [&](int buf, int c) {
        uint32_t sb = smb + buf * BUF;
        if (MODE == 0) {
#pragma unroll
            for (int i = 0; i < 6; i++) {
                int idx = t + 256 * i;
                int tile = idx >> 9, r = (idx >> 2) & 127, s = idx & 3;
                const uint16_t* base = (tile == 0) ? Ah : (tile == 1) ? Al : Bh;
                cp16(sb + (uint32_t)tile * TILE_B + r * 80 + s * 16,
                     base + (size_t)r * HID + c * 32 + s * 8);
            }
        } else if (MODE == 1) {
            // A fp32: 128 rows x 128B, 136B pitch, 8B copies (2048 / 256 = 8 each)
#pragma unroll
            for (int i = 0; i < 8; i++) {
                int idx = t + 256 * i;
                int r = idx >> 4, s = idx & 15;
                cp8(sb + r * 136 + s * 8, Afp32 + (size_t)r * HID + c * 32 + s * 2);
            }
            // B fp16
#pragma unroll
            for (int i = 0; i < 2; i++) {
                int idx = t + 256 * i;
                int r = (idx >> 2) & 127, s = idx & 3;
                cp16(sb + BOFF + r * 80 + s * 16, Bh + (size_t)r * HID + c * 32 + s * 8);
            }
        } else if (MODE == 2) {
#pragma unroll
            for (int i = 0; i < 4; i++) {
                int idx = t + 256 * i;
                int tile = idx >> 9, r = (idx >> 2) & 127, s = idx & 3;
                const uint16_t* base = tile ? Bh : Ah;
                cp16(sb + (tile ? BOFF : 0u) + r * 80 + s * 16,
                     base + (size_t)r * 128 + c * 32 + s * 8);
            }
        } else {
            // MODE 3 B: vh rows [c*32,+32) x 128 d, 272B pitch
#pragma unroll
            for (int i = 0; i < 2; i++) {
                int idx = t + 256 * i;
                int r = idx >> 4, s = idx & 15;
                cp16(sb + BOFF + r * 272 + s * 16, Bh + (size_t)(c * 32 + r) * 128 + s * 8);
            }
        }
    };

    // MODE 1: smem fp32 -> fp16 A conversion (float2 loads: 136B pitch is 8B aligned)
    auto cvt_a = [&](int buf) {
        char* bb = sm + buf * BUF;
        const int r = t >> 1, h = t & 1;
        const char* src = bb + r * 136 + h * 64;
        float2 x[8];
#pragma unroll
        for (int j = 0; j < 8; j++) x[j] = *(const float2*)(src + j * 8);
        uint4 H;
        H.x = pk2h(x[0].x, x[0].y); H.y = pk2h(x[1].x, x[1].y);
        H.z = pk2h(x[2].x, x[2].y); H.w = pk2h(x[3].x, x[3].y);
        *(uint4*)(bb + AOFF + r * 80 + h * 32) = H;
        H.x = pk2h(x[4].x, x[4].y); H.y = pk2h(x[5].x, x[5].y);
        H.z = pk2h(x[6].x, x[6].y); H.w = pk2h(x[7].x, x[7].y);
        *(uint4*)(bb + AOFF + r * 80 + h * 32 + 16) = H;
    };

    auto compute = [&](uint32_t sbuf) {
#pragma unroll
        for (int ks = 0; ks < 2; ks++) {
            const uint32_t rowsel = (uint32_t)(lane & 15) * 80
                                  + (uint32_t)((lane >> 4) + ks * 2) * 16;
            uint32_t aH[2][4], bH[4][4];
#pragma unroll
            for (int mt = 0; mt < 2; mt++)
                ldm4(aH[mt], sbuf + AOFF + (uint32_t)(wm0 + mt * 16) * 80 + rowsel);
            if (MODE == 3) {
                const uint32_t rsel = (uint32_t)((lane & 7) + ((lane >> 4) << 3) + ks * 16) * 272
                                    + (uint32_t)(((lane >> 3) & 1) << 4);
#pragma unroll
                for (int g = 0; g < 4; g++)
                    ldm4t(bH[g], sbuf + BOFF + rsel + (uint32_t)(wn0 + g * 16) * 2);
            } else {
#pragma unroll
                for (int g = 0; g < 4; g++)
                    ldm4(bH[g], sbuf + BOFF + (uint32_t)(wn0 + g * 16) * 80 + rowsel);
            }
#pragma unroll
            for (int mt = 0; mt < 2; mt++)
#pragma unroll
                for (int g = 0; g < 4; g++) {
                    mma16816(acc[mt][2 * g],     aH[mt], bH[g][0], bH[g][2]);
                    mma16816(acc[mt][2 * g + 1], aH[mt], bH[g][1], bH[g][3]);
                }
            if (NPA == 2) {
#pragma unroll
                for (int mt = 0; mt < 2; mt++)
                    ldm4(aH[mt], sbuf + TILE_B + (uint32_t)(wm0 + mt * 16) * 80 + rowsel);
#pragma unroll
                for (int mt = 0; mt < 2; mt++)
#pragma unroll
                    for (int g = 0; g < 4; g++) {
                        mma16816(acc[mt][2 * g],     aH[mt], bH[g][0], bH[g][2]);
                        mma16816(acc[mt][2 * g + 1], aH[mt], bH[g][1], bH[g][3]);
                    }
            }
        }
    };

    // ---- MODE 3 register A path: e fp16 -> P = e*corr, write attn, fp16 smem ----
    uint4 eArg[2];
    const uint16_t* apA = REGA ? Ae + (size_t)(t >> 1) * VL + (t & 1) * 16 : nullptr;
    float* awA = REGA ? attw + (size_t)(t >> 1) * VL + (t & 1) * 16 : nullptr;
    const uint32_t aoff = (t >> 1) * 80 + (t & 1) * 32;

    auto LD_A = [&](int c) {
        eArg[0] = *(const uint4*)(apA + (size_t)c * 32);
        eArg[1] = *(const uint4*)(apA + (size_t)c * 32 + 8);
    };
    auto STS_A = [&](int buf, int ch) {
        char* bb = sm + buf * BUF;
        float cr = __expf(mpRow[(ch >> 2) * 128] - m_st) * li_st;
        float* aw = awA + (size_t)ch * 32;
#pragma unroll
        for (int half = 0; half < 2; half++) {
            uint32_t e4[4] = {eArg[half].x, eArg[half].y, eArg[half].z, eArg[half].w};
            uint4 H;
            uint32_t* Hp = (uint32_t*)&H;
#pragma unroll
            for (int j = 0; j < 4; j++) {
                float2 e = up2h(e4[j]);
                float p0 = e.x * cr, p1 = e.y * cr;
                *(float2*)(aw + half * 8 + j * 2) = make_float2(p0, p1);
                Hp[j] = pk2h(p0, p1);
            }
            *(uint4*)(bb + aoff + half * 16) = H;
        }
    };

    // ---- prologue ----
    if (REGA) {
        LD_A(0); STS_A(0, 0);
        LD_A(1); STS_A(1, 1);
        LD_A(2); STS_A(2, 2);
        LD_A(3);
    }
    cp_chunk(0, 0); CP_COMMIT();
    cp_chunk(1, 1); CP_COMMIT();
    cp_chunk(2, 2); CP_COMMIT();

    int buf = 0;
    for (int c = 0; c < NC; c++) {
        CP_WAIT2();
        __syncthreads();
        if (MODE == 1) { cvt_a(buf); __syncthreads(); }
        compute(smb + buf * BUF);
        __syncthreads();
        if (c + 3 < NC) {
            if (REGA) STS_A(buf, c + 3);
            cp_chunk(buf, c + 3);
        }
        CP_COMMIT();
        if (REGA && c + 4 < NC) LD_A(c + 4);
        buf = (buf == 2) ? 0 : buf + 1;
    }

    // ------------------------- epilogues -------------------------
    if (MODE == 2) {
        // g_eh <- e = exp(s*sc - m_tile) fp16; partials -> g_mp/g_lp
        float* pm = (float*)(sm + 34048);
        float* mM = pm + 256;
        float* pl = mM + 128;
        const float sc = 0.08838834764831845f;
#pragma unroll
        for (int mt = 0; mt < 2; mt++)
#pragma unroll
            for (int h2 = 0; h2 < 2; h2++) {
                const int row = wm0 + mt * 16 + (lane >> 2) + h2 * 8;
                float mx = -1e30f;
#pragma unroll
                for (int nt = 0; nt < 8; nt++)
                    mx = fmaxf(mx, fmaxf(acc[mt][nt][2 * h2], acc[mt][nt][2 * h2 + 1]));
                mx *= sc;
                mx = fmaxf(mx, __shfl_xor_sync(~0u, mx, 1));
                mx = fmaxf(mx, __shfl_xor_sync(~0u, mx, 2));
                if ((lane & 3) == 0) pm[(w >> 2) * 128 + row] = mx;
            }
        __syncthreads();
        if (t < 128) mM[t] = fmaxf(pm[t], pm[128 + t]);
        __syncthreads();
#pragma unroll
        for (int mt = 0; mt < 2; mt++)
#pragma unroll
            for (int h2 = 0; h2 < 2; h2++) {
                const int row = wm0 + mt * 16 + (lane >> 2) + h2 * 8;
                const float mm = mM[row];
                uint16_t* ed = g_eh + ((size_t)blockIdx.y * QL + row) * VL + blockIdx.x * 128;
                float l = 0.f;
#pragma unroll
                for (int nt = 0; nt < 8; nt++) {
                    const int col = wn0 + nt * 8 + 2 * (lane & 3);
                    float e0 = __expf(acc[mt][nt][2 * h2]     * sc - mm);
                    float e1 = __expf(acc[mt][nt][2 * h2 + 1] * sc - mm);
                    *(uint32_t*)(ed + col) = pk2h(e0, e1);
                    l += e0 + e1;
                }
                l += __shfl_xor_sync(~0u, l, 1);
                l += __shfl_xor_sync(~0u, l, 2);
                if ((lane & 3) == 0) pl[(w >> 2) * 128 + row] = l;
            }
        __syncthreads();
        if (t < 128) {
            size_t o = ((size_t)blockIdx.y * 16 + blockIdx.x) * 128 + t;
            g_mp[o] = mM[t];
            g_lp[o] = pl[t] + pl[128 + t];
        }
        return;
    }

    float* vec = (float*)(sm + 40960);
    if (MODE == 0) {
        if (t < 128) vec[t] = biasv[blockIdx.x * 128 + t];
    }
    if (MODE == 1) {
        if (t < 128) {
            vec[t]       = biasv[blockIdx.x * 128 + t] + g_Cc[t];
            vec[128 + t] = g_A0[t];
            vec[256 + t] = g_A1[t];
            vec[384 + t] = g_A2[t];
        }
        const int b = blockIdx.y >> 4, h = blockIdx.x;
        const int vpos0 = (blockIdx.y & 15) * 128;
        const float* lar = la + (size_t)(b * 8 + h) * VL;
        if (t < 130) {
            int g = vpos0 - 1 + t;
            vec[512 + t] = (g >= 0 && g < VL) ? lar[g] : 0.f;
        }
    }
    __syncthreads();

#pragma unroll
    for (int mt = 0; mt < 2; mt++) {
#pragma unroll
        for (int h2 = 0; h2 < 2; h2++) {
            const int row = wm0 + mt * 16 + (lane >> 2) + h2 * 8;
            size_t obase = 0;
            float* dst = nullptr;
            float lm1 = 0.f, l0 = 0.f, lp1 = 0.f;
            if (MODE == 0) {
                obase = (((size_t)(blockIdx.x * 32 + blockIdx.y)) * QL + row) * 128;
            } else if (MODE == 1) {
                int b = blockIdx.y >> 4, h = blockIdx.x;
                int vpos0 = (blockIdx.y & 15) * 128;
                lm1 = vec[512 + row]; l0 = vec[513 + row]; lp1 = vec[514 + row];
                obase = (((size_t)(h * 32 + b)) * VL + vpos0 + row) * 128;
            } else {
                int h = blockIdx.x >> 5, b = blockIdx.x & 31;
                dst = dsto + ((size_t)(b * QL + row)) * HID + h * 128;
            }
#pragma unroll
            for (int nt = 0; nt < 8; nt++) {
                const int col = wn0 + nt * 8 + 2 * (lane & 3);
                float x = acc[mt][nt][2 * h2];
                float y = acc[mt][nt][2 * h2 + 1];
                if (MODE == 0) {
                    x += vec[col]; y += vec[col + 1];
                    *(uint32_t*)&g_qh_h[obase + col] = pk2h(x, y);
                } else if (MODE == 1) {
                    x += vec[col]     + vec[128 + col]     * lm1 + vec[256 + col]     * l0 + vec[384 + col]     * lp1;
                    y += vec[col + 1] + vec[128 + col + 1] * lm1 + vec[256 + col + 1] * l0 + vec[384 + col + 1] * lp1;
                    *(uint32_t*)&g_vh_h[obase + col] = pk2h(x, y);
                } else {
                    *(float2*)(dst + col) = make_float2(x, y);
                }
            }
        }
    }
}

// ---------------------------------------------------------------------------
// fp32 -> fp16 splits
// ---------------------------------------------------------------------------
DI void split2_body(const float4* __restrict__ in, uint16_t* oh, uint16_t* ol, int n4) {
    int i = blockIdx.x * 256 + threadIdx.x;
    if (i >= n4) return;
    float4 x = in[i];
    uint32_t l0, l1;
    uint32_t h0 = sp2h(x.x, x.y, l0), h1 = sp2h(x.z, x.w, l1);
    uint2 H; H.x = h0; H.y = h1;
    *(uint2*)&oh[(size_t)i * 4] = H;
    uint2 L; L.x = l0; L.y = l1;
    *(uint2*)&ol[(size_t)i * 4] = L;
}
DI void split1_body(const float4* __restrict__ in, uint16_t* oh, int n4) {
    int i = blockIdx.x * 256 + threadIdx.x;
    if (i >= n4) return;
    float4 x = in[i];
    uint2 H;
    H.x = pk2h(x.x, x.y); H.y = pk2h(x.z, x.w);
    *(uint2*)&oh[(size_t)i * 4] = H;
}
__global__ void split_q_k(const float4* in)  { split2_body(in, s_q_h, s_q_l, 1048576); }
__global__ void split_wq_k(const float4* in) { split1_body(in, s_Wq_h, 262144); }
__global__ void split_wv_k(const float4* in) { split1_body(in, s_Wv_h, 262144); }

// ---------------------------------------------------------------------------
__global__ void prep_kernel(const float* __restrict__ conv_w,
                            const float* __restrict__ conv_b,
                            const float* __restrict__ Wloc)
{
    int d = threadIdx.x;
    float a0 = 0.f, a1 = 0.f, a2 = 0.f, c = 0.f;
#pragma unroll
    for (int cc = 0; cc < 10; cc++) {
        float wl = Wloc[d * 10 + cc];
        a0 += wl * conv_w[cc * 3 + 0];
        a1 += wl * conv_w[cc * 3 + 1];
        a2 += wl * conv_w[cc * 3 + 2];
        c  += wl * conv_b[cc];
    }
    g_A0[d] = a0; g_A1[d] = a1; g_A2[d] = a2; g_Cc[d] = c;
}

// ---------------------------------------------------------------------------
extern "C" void kernel_launch(void* const* d_in, const int* in_sizes, int n_in,
                              void* d_out, int out_size)
{
    const float* q         = (const float*)d_in[0];
    const float* v         = (const float*)d_in[1];
    const float* last_attn = (const float*)d_in[2];
    const float* conv_w    = (const float*)d_in[3];
    const float* conv_b    = (const float*)d_in[4];
    const float* Wq        = (const float*)d_in[5];
    const float* bq        = (const float*)d_in[6];
    const float* Wv        = (const float*)d_in[7];
    const float* Wloc      = (const float*)d_in[8];
    const float* bias      = (const float*)d_in[9];

    float* out = (float*)d_out;

    const int SM0 = 3 * 3 * TILE_B;            // 92160
    const int SM1 = 3 * (A32_B + 2 * TILE_B);  // 113664
    const int SM2 = 3 * 2 * TILE_B;            // 61440
    const int SMO = 3 * (TILE_B + BT3);        // 56832

    static cudaStream_t s2 = nullptr;
    static cudaEvent_t evR = nullptr, evJ = nullptr;
    if (!s2) {
        cudaFuncSetAttribute(mma_gemm<0>, cudaFuncAttributeMaxDynamicSharedMemorySize, SM0);
        cudaFuncSetAttribute(mma_gemm<1>, cudaFuncAttributeMaxDynamicSharedMemorySize, SM1);
        cudaFuncSetAttribute(mma_gemm<2>, cudaFuncAttributeMaxDynamicSharedMemorySize, SM2);
        cudaFuncSetAttribute(mma_gemm<3>, cudaFuncAttributeMaxDynamicSharedMemorySize, SMO);
        cudaStreamCreateWithFlags(&s2, cudaStreamNonBlocking);
        cudaEventCreateWithFlags(&evR, cudaEventDisableTiming);
        cudaEventCreateWithFlags(&evJ, cudaEventDisableTiming);
    }

    // fork: qp chain on s2, vp chain on default stream
    cudaEventRecord(evR, 0);
    cudaStreamWaitEvent(s2, evR, 0);

    split_q_k <<<4096, 256, 0, s2>>>((const float4*)q);
    split_wq_k<<<1024, 256, 0, s2>>>((const float4*)Wq);
    mma_gemm<0><<<dim3(8, 32), 256, SM0, s2>>>(nullptr, bq, nullptr, nullptr);
    cudaEventRecord(evJ, s2);

    prep_kernel<<<1, 128>>>(conv_w, conv_b, Wloc);
    split_wv_k<<<1024, 256>>>((const float4*)Wv);
    mma_gemm<1><<<dim3(8, 512), 256, SM1>>>(v, bias, last_attn, nullptr);

    // join: score needs qp (s2) and vp (default)
    cudaStreamWaitEvent(0, evJ, 0);
    mma_gemm<2><<<dim3(16, 256), 256, SM2>>>(nullptr, nullptr, nullptr, nullptr);
    mma_gemm<3><<<256, 256, SMO>>>(nullptr, nullptr, nullptr, out);
}

// round 15
// speedup vs baseline: 1.0565x; 1.0565x over previous
#include <cuda_runtime.h>
#include <cuda_fp16.h>
#include <cstdint>

#define DI __device__ __forceinline__

static const int QL  = 128;
static const int VL  = 2048;
static const int HID = 1024;

// ---------------------------------------------------------------------------
// Scratch (device globals; no runtime allocation allowed). fp16 operands.
// ---------------------------------------------------------------------------
__device__ uint16_t s_q_h[4194304], s_q_l[4194304];     // split q (2-pass A)
__device__ uint16_t s_v_h[67108864];                    // v hi (1-pass A)
__device__ uint16_t s_Wq_h[1048576];                    // Wq hi
__device__ uint16_t s_Wv_h[1048576];                    // Wv hi
__device__ uint16_t g_qh_h[4194304];                    // qp result [n][q][d]
__device__ uint16_t g_vh_h[67108864];                   // vp result [n][v][d]
__device__ uint16_t g_eh[67108864];                     // score e-values fp16 [n][q][v]
__device__ float g_A0[128], g_A1[128], g_A2[128], g_Cc[128];
__device__ float g_mp[524288], g_lp[524288];            // softmax partials [n][16][128]

// ---------------------------------------------------------------------------
DI uint32_t smem_u32(const void* p) {
    uint32_t a;
    asm("{ .reg .u64 t; cvta.to.shared.u64 t, %1; cvt.u32.u64 %0, t; }" : "=r"(a) : "l"(p));
    return a;
}

DI uint32_t sp2h(float a, float b, uint32_t& lo) {
    __half2 h = __floats2half2_rn(a, b);
    float2 f = __half22float2(h);
    __half2 l = __floats2half2_rn(a - f.x, b - f.y);
    lo = *(uint32_t*)&l;
    return *(uint32_t*)&h;
}
DI uint32_t pk2h(float a, float b) {
    __half2 h = __floats2half2_rn(a, b);
    return *(uint32_t*)&h;
}
DI float2 up2h(uint32_t v) {
    return __half22float2(*(__half2*)&v);
}

DI void ldm4(uint32_t* r, uint32_t a) {
    asm volatile("ldmatrix.sync.aligned.m8n8.x4.shared.b16 {%0,%1,%2,%3}, [%4];"
        : "=r"(r[0]), "=r"(r[1]), "=r"(r[2]), "=r"(r[3]) : "r"(a));
}
DI void ldm4t(uint32_t* r, uint32_t a) {
    asm volatile("ldmatrix.sync.aligned.m8n8.x4.trans.shared.b16 {%0,%1,%2,%3}, [%4];"
        : "=r"(r[0]), "=r"(r[1]), "=r"(r[2]), "=r"(r[3]) : "r"(a));
}

DI void mma16816(float* d, const uint32_t* a, uint32_t b0, uint32_t b1) {
    asm volatile("mma.sync.aligned.m16n8k16.row.col.f32.f16.f16.f32 "
        "{%0,%1,%2,%3},{%4,%5,%6,%7},{%8,%9},{%0,%1,%2,%3};"
        : "+f"(d[0]), "+f"(d[1]), "+f"(d[2]), "+f"(d[3])
        : "r"(a[0]), "r"(a[1]), "r"(a[2]), "r"(a[3]), "r"(b0), "r"(b1));
}

DI void cp16(uint32_t dst, const void* src) {
    asm volatile("cp.async.cg.shared.global [%0], [%1], 16;" :: "r"(dst), "l"(src));
}
#define CP_COMMIT() asm volatile("cp.async.commit_group;" ::: "memory")
#define CP_WAIT2()  asm volatile("cp.async.wait_group 2;"  ::: "memory")

static const int TILE_B = 10240;
static const int BT3    = 8704;          // MODE 3 B tile: 32 rows x 272B

// ---------------------------------------------------------------------------
// Unified GEMM, 128x128 tile, 3-stage pipeline, 2 CTAs/SM.
// MODE 0: qp = q@Wq^T + bq       -> g_qh_h       grid(8, 32)  cp.async A, 2-pass
// MODE 1: vp = v@Wv^T + bias+loc -> g_vh_h       grid(8, 512) cp.async A, 1-pass
// MODE 2: score: e=exp(s-m_tile) -> g_eh + (m,l) grid(16,256) cp.async A, 1-pass
// MODE 3: out = P@vh, P=e*corr   -> out; attn=P  grid(256)    reg A fp16 e; B trans
// ---------------------------------------------------------------------------
template <int MODE>
__global__ void __launch_bounds__(256, 2)
mma_gemm(const float* __restrict__ Ain, const float* __restrict__ biasv,
         const float* __restrict__ la, float* __restrict__ dsto)
{
    extern __shared__ char sm[];
    const uint32_t smb = smem_u32(sm);
    const int t = threadIdx.x, lane = t & 31, w = t >> 5;
    const int wm0 = (w & 3) * 32, wn0 = (w >> 2) * 64;

    constexpr int  K    = (MODE < 2) ? HID : (MODE == 2 ? 128 : VL);
    constexpr int  NC   = K / 32;
    constexpr int  NPA  = (MODE == 0) ? 2 : 1;
    constexpr int  NT   = (MODE == 0) ? 3 : 2;
    constexpr int  BUF  = (MODE == 3) ? (TILE_B + BT3) : NT * TILE_B;
    constexpr uint32_t BOFF = (MODE == 3) ? (uint32_t)TILE_B
                                          : (uint32_t)(NT - 1) * TILE_B;
    constexpr bool REGA = (MODE == 3);
    constexpr int  LD   = (MODE < 2) ? HID : 128;   // A/B row stride (modes 0/1/2)

    const uint16_t *Ah = nullptr, *Al = nullptr, *Bh = nullptr;
    const uint16_t* Ae = nullptr;
    float* attw = nullptr;
    const float* mpRow = nullptr;
    float m_st = 0.f, li_st = 0.f;
    if (MODE == 0) {
        size_t ao = (size_t)blockIdx.y * 128 * HID, bo = (size_t)blockIdx.x * 128 * HID;
        Ah = s_q_h + ao; Al = s_q_l + ao; Bh = s_Wq_h + bo;
    } else if (MODE == 1) {
        size_t ao = (size_t)blockIdx.y * 128 * HID, bo = (size_t)blockIdx.x * 128 * HID;
        Ah = s_v_h + ao; Bh = s_Wv_h + bo;
    } else if (MODE == 2) {
        Ah = g_qh_h + (size_t)blockIdx.y * QL * 128;
        Bh = g_vh_h + (size_t)blockIdx.y * VL * 128 + (size_t)blockIdx.x * 128 * 128;
    } else {
        Ae   = g_eh + (size_t)blockIdx.x * QL * VL;
        attw = dsto + 4194304 + (size_t)blockIdx.x * QL * VL;   // attn region
        Bh   = g_vh_h + (size_t)blockIdx.x * VL * 128;
        const int myrow = t >> 1;
        mpRow = g_mp + (size_t)blockIdx.x * 2048 + myrow;
        const float* lp = g_lp + (size_t)blockIdx.x * 2048 + myrow;
        float m = -1e30f;
#pragma unroll
        for (int i = 0; i < 16; i++) m = fmaxf(m, mpRow[i * 128]);
        float l = 0.f;
#pragma unroll
        for (int i = 0; i < 16; i++) l += lp[i * 128] * __expf(mpRow[i * 128] - m);
        m_st = m; li_st = 1.0f / l;
    }

    float acc[2][8][4];
#pragma unroll
    for (int i = 0; i < 2; i++)
#pragma unroll
        for (int j = 0; j < 8; j++)
#pragma unroll
            for (int k = 0; k < 4; k++) acc[i][j][k] = 0.f;

    // ---- cp.async loaders ----
    auto cp_chunk = [&](int buf, int c) {
        uint32_t sb = smb + buf * BUF;
        if (MODE == 3) {
            // B: vh rows [c*32,+32) x 128 d, 272B pitch
#pragma unroll
            for (int i = 0; i < 2; i++) {
                int idx = t + 256 * i;
                int r = idx >> 4, s = idx & 15;
                cp16(sb + BOFF + r * 272 + s * 16, Bh + (size_t)(c * 32 + r) * 128 + s * 8);
            }
        } else {
#pragma unroll
            for (int i = 0; i < NT * 2; i++) {
                int idx = t + 256 * i;
                int tile = idx >> 9, r = (idx >> 2) & 127, s = idx & 3;
                const uint16_t* base; uint32_t doff;
                if (NT == 2) { base = tile ? Bh : Ah; doff = tile ? TILE_B : 0u; }
                else {
                    base = (tile == 0) ? Ah : (tile == 1) ? Al : Bh;
                    doff = (uint32_t)tile * TILE_B;
                }
                cp16(sb + doff + r * 80 + s * 16, base + (size_t)r * LD + c * 32 + s * 8);
            }
        }
    };

    auto compute = [&](uint32_t sbuf) {
#pragma unroll
        for (int ks = 0; ks < 2; ks++) {
            const uint32_t rowsel = (uint32_t)(lane & 15) * 80
                                  + (uint32_t)((lane >> 4) + ks * 2) * 16;
            uint32_t aH[2][4], bH[4][4];
#pragma unroll
            for (int mt = 0; mt < 2; mt++)
                ldm4(aH[mt], sbuf + (uint32_t)(wm0 + mt * 16) * 80 + rowsel);
            if (MODE == 3) {
                const uint32_t rsel = (uint32_t)((lane & 7) + ((lane >> 4) << 3) + ks * 16) * 272
                                    + (uint32_t)(((lane >> 3) & 1) << 4);
#pragma unroll
                for (int g = 0; g < 4; g++)
                    ldm4t(bH[g], sbuf + BOFF + rsel + (uint32_t)(wn0 + g * 16) * 2);
            } else {
#pragma unroll
                for (int g = 0; g < 4; g++)
                    ldm4(bH[g], sbuf + BOFF + (uint32_t)(wn0 + g * 16) * 80 + rowsel);
            }
#pragma unroll
            for (int mt = 0; mt < 2; mt++)
#pragma unroll
                for (int g = 0; g < 4; g++) {
                    mma16816(acc[mt][2 * g],     aH[mt], bH[g][0], bH[g][2]);
                    mma16816(acc[mt][2 * g + 1], aH[mt], bH[g][1], bH[g][3]);
                }
            if (NPA == 2) {
#pragma unroll
                for (int mt = 0; mt < 2; mt++)
                    ldm4(aH[mt], sbuf + TILE_B + (uint32_t)(wm0 + mt * 16) * 80 + rowsel);
#pragma unroll
                for (int mt = 0; mt < 2; mt++)
#pragma unroll
                    for (int g = 0; g < 4; g++) {
                        mma16816(acc[mt][2 * g],     aH[mt], bH[g][0], bH[g][2]);
                        mma16816(acc[mt][2 * g + 1], aH[mt], bH[g][1], bH[g][3]);
                    }
            }
        }
    };

    // ---- MODE 3 register A path: e fp16 -> P = e*corr, write attn, fp16 smem ----
    uint4 eArg[2];
    const uint16_t* apA = REGA ? Ae + (size_t)(t >> 1) * VL + (t & 1) * 16 : nullptr;
    float* awA = REGA ? attw + (size_t)(t >> 1) * VL + (t & 1) * 16 : nullptr;
    const uint32_t aoff = (t >> 1) * 80 + (t & 1) * 32;

    auto LD_A = [&](int c) {
        eArg[0] = *(const uint4*)(apA + (size_t)c * 32);
        eArg[1] = *(const uint4*)(apA + (size_t)c * 32 + 8);
    };
    auto STS_A = [&](int buf, int ch) {
        char* bb = sm + buf * BUF;
        float cr = __expf(mpRow[(ch >> 2) * 128] - m_st) * li_st;
        float* aw = awA + (size_t)ch * 32;
#pragma unroll
        for (int half = 0; half < 2; half++) {
            uint32_t e4[4] = {eArg[half].x, eArg[half].y, eArg[half].z, eArg[half].w};
            uint4 H;
            uint32_t* Hp = (uint32_t*)&H;
#pragma unroll
            for (int j = 0; j < 4; j++) {
                float2 e = up2h(e4[j]);
                float p0 = e.x * cr, p1 = e.y * cr;
                *(float2*)(aw + half * 8 + j * 2) = make_float2(p0, p1);
                Hp[j] = pk2h(p0, p1);
            }
            *(uint4*)(bb + aoff + half * 16) = H;
        }
    };

    // ---- prologue ----
    if (REGA) {
        LD_A(0); STS_A(0, 0);
        LD_A(1); STS_A(1, 1);
        LD_A(2); STS_A(2, 2);
        LD_A(3);
    }
    cp_chunk(0, 0); CP_COMMIT();
    cp_chunk(1, 1); CP_COMMIT();
    cp_chunk(2, 2); CP_COMMIT();

    int buf = 0;
    for (int c = 0; c < NC; c++) {
        CP_WAIT2();
        __syncthreads();
        compute(smb + buf * BUF);
        __syncthreads();
        if (c + 3 < NC) {
            if (REGA) STS_A(buf, c + 3);
            cp_chunk(buf, c + 3);
        }
        CP_COMMIT();
        if (REGA && c + 4 < NC) LD_A(c + 4);
        buf = (buf == 2) ? 0 : buf + 1;
    }

    // ------------------------- epilogues -------------------------
    if (MODE == 2) {
        // g_eh <- e = exp(s*sc - m_tile) fp16; partials -> g_mp/g_lp
        float* pm = (float*)(sm + 34048);
        float* mM = pm + 256;
        float* pl = mM + 128;
        const float sc = 0.08838834764831845f;
#pragma unroll
        for (int mt = 0; mt < 2; mt++)
#pragma unroll
            for (int h2 = 0; h2 < 2; h2++) {
                const int row = wm0 + mt * 16 + (lane >> 2) + h2 * 8;
                float mx = -1e30f;
#pragma unroll
                for (int nt = 0; nt < 8; nt++)
                    mx = fmaxf(mx, fmaxf(acc[mt][nt][2 * h2], acc[mt][nt][2 * h2 + 1]));
                mx *= sc;
                mx = fmaxf(mx, __shfl_xor_sync(~0u, mx, 1));
                mx = fmaxf(mx, __shfl_xor_sync(~0u, mx, 2));
                if ((lane & 3) == 0) pm[(w >> 2) * 128 + row] = mx;
            }
        __syncthreads();
        if (t < 128) mM[t] = fmaxf(pm[t], pm[128 + t]);
        __syncthreads();
#pragma unroll
        for (int mt = 0; mt < 2; mt++)
#pragma unroll
            for (int h2 = 0; h2 < 2; h2++) {
                const int row = wm0 + mt * 16 + (lane >> 2) + h2 * 8;
                const float mm = mM[row];
                uint16_t* ed = g_eh + ((size_t)blockIdx.y * QL + row) * VL + blockIdx.x * 128;
                float l = 0.f;
#pragma unroll
                for (int nt = 0; nt < 8; nt++) {
                    const int col = wn0 + nt * 8 + 2 * (lane & 3);
                    float e0 = __expf(acc[mt][nt][2 * h2]     * sc - mm);
                    float e1 = __expf(acc[mt][nt][2 * h2 + 1] * sc - mm);
                    *(uint32_t*)(ed + col) = pk2h(e0, e1);
                    l += e0 + e1;
                }
                l += __shfl_xor_sync(~0u, l, 1);
                l += __shfl_xor_sync(~0u, l, 2);
                if ((lane & 3) == 0) pl[(w >> 2) * 128 + row] = l;
            }
        __syncthreads();
        if (t < 128) {
            size_t o = ((size_t)blockIdx.y * 16 + blockIdx.x) * 128 + t;
            g_mp[o] = mM[t];
            g_lp[o] = pl[t] + pl[128 + t];
        }
        return;
    }

    float* vec = (float*)(sm + 34048);
    if (MODE == 0) {
        if (t < 128) vec[t] = biasv[blockIdx.x * 128 + t];
    }
    if (MODE == 1) {
        if (t < 128) {
            vec[t]       = biasv[blockIdx.x * 128 + t] + g_Cc[t];
            vec[128 + t] = g_A0[t];
            vec[256 + t] = g_A1[t];
            vec[384 + t] = g_A2[t];
        }
        const int b = blockIdx.y >> 4, h = blockIdx.x;
        const int vpos0 = (blockIdx.y & 15) * 128;
        const float* lar = la + (size_t)(b * 8 + h) * VL;
        if (t < 130) {
            int g = vpos0 - 1 + t;
            vec[512 + t] = (g >= 0 && g < VL) ? lar[g] : 0.f;
        }
    }
    __syncthreads();

#pragma unroll
    for (int mt = 0; mt < 2; mt++) {
#pragma unroll
        for (int h2 = 0; h2 < 2; h2++) {
            const int row = wm0 + mt * 16 + (lane >> 2) + h2 * 8;
            size_t obase = 0;
            float* dst = nullptr;
            float lm1 = 0.f, l0 = 0.f, lp1 = 0.f;
            if (MODE == 0) {
                obase = (((size_t)(blockIdx.x * 32 + blockIdx.y)) * QL + row) * 128;
            } else if (MODE == 1) {
                int b = blockIdx.y >> 4, h = blockIdx.x;
                int vpos0 = (blockIdx.y & 15) * 128;
                lm1 = vec[512 + row]; l0 = vec[513 + row]; lp1 = vec[514 + row];
                obase = (((size_t)(h * 32 + b)) * VL + vpos0 + row) * 128;
            } else {
                int h = blockIdx.x >> 5, b = blockIdx.x & 31;
                dst = dsto + ((size_t)(b * QL + row)) * HID + h * 128;
            }
#pragma unroll
            for (int nt = 0; nt < 8; nt++) {
                const int col = wn0 + nt * 8 + 2 * (lane & 3);
                float x = acc[mt][nt][2 * h2];
                float y = acc[mt][nt][2 * h2 + 1];
                if (MODE == 0) {
                    x += vec[col]; y += vec[col + 1];
                    *(uint32_t*)&g_qh_h[obase + col] = pk2h(x, y);
                } else if (MODE == 1) {
                    x += vec[col]     + vec[128 + col]     * lm1 + vec[256 + col]     * l0 + vec[384 + col]     * lp1;
                    y += vec[col + 1] + vec[128 + col + 1] * lm1 + vec[256 + col + 1] * l0 + vec[384 + col + 1] * lp1;
                    *(uint32_t*)&g_vh_h[obase + col] = pk2h(x, y);
                } else {
                    *(float2*)(dst + col) = make_float2(x, y);
                }
            }
        }
    }
}

// ---------------------------------------------------------------------------
// fp32 -> fp16 splits
// ---------------------------------------------------------------------------
DI void split2_body(const float4* __restrict__ in, uint16_t* oh, uint16_t* ol, int n4) {
    int i = blockIdx.x * 256 + threadIdx.x;
    if (i >= n4) return;
    float4 x = in[i];
    uint32_t l0, l1;
    uint32_t h0 = sp2h(x.x, x.y, l0), h1 = sp2h(x.z, x.w, l1);
    uint2 H; H.x = h0; H.y = h1;
    *(uint2*)&oh[(size_t)i * 4] = H;
    uint2 L; L.x = l0; L.y = l1;
    *(uint2*)&ol[(size_t)i * 4] = L;
}
DI void split1_body(const float4* __restrict__ in, uint16_t* oh, int n4) {
    int i = blockIdx.x * 256 + threadIdx.x;
    if (i >= n4) return;
    float4 x = in[i];
    uint2 H;
    H.x = pk2h(x.x, x.y); H.y = pk2h(x.z, x.w);
    *(uint2*)&oh[(size_t)i * 4] = H;
}
__global__ void split_q_k(const float4* in)  { split2_body(in, s_q_h, s_q_l, 1048576); }
__global__ void split_v_k(const float4* in)  { split1_body(in, s_v_h, 16777216); }
__global__ void split_wq_k(const float4* in) { split1_body(in, s_Wq_h, 262144); }
__global__ void split_wv_k(const float4* in) { split1_body(in, s_Wv_h, 262144); }

// ---------------------------------------------------------------------------
__global__ void prep_kernel(const float* __restrict__ conv_w,
                            const float* __restrict__ conv_b,
                            const float* __restrict__ Wloc)
{
    int d = threadIdx.x;
    float a0 = 0.f, a1 = 0.f, a2 = 0.f, c = 0.f;
#pragma unroll
    for (int cc = 0; cc < 10; cc++) {
        float wl = Wloc[d * 10 + cc];
        a0 += wl * conv_w[cc * 3 + 0];
        a1 += wl * conv_w[cc * 3 + 1];
        a2 += wl * conv_w[cc * 3 + 2];
        c  += wl * conv_b[cc];
    }
    g_A0[d] = a0; g_A1[d] = a1; g_A2[d] = a2; g_Cc[d] = c;
}

// ---------------------------------------------------------------------------
extern "C" void kernel_launch(void* const* d_in, const int* in_sizes, int n_in,
                              void* d_out, int out_size)
{
    const float* q         = (const float*)d_in[0];
    const float* v         = (const float*)d_in[1];
    const float* last_attn = (const float*)d_in[2];
    const float* conv_w    = (const float*)d_in[3];
    const float* conv_b    = (const float*)d_in[4];
    const float* Wq        = (const float*)d_in[5];
    const float* bq        = (const float*)d_in[6];
    const float* Wv        = (const float*)d_in[7];
    const float* Wloc      = (const float*)d_in[8];
    const float* bias      = (const float*)d_in[9];

    float* out = (float*)d_out;

    const int SM0 = 3 * 3 * TILE_B;        // 92160 (mode 0)
    const int SM2 = 3 * 2 * TILE_B;        // 61440 (modes 1/2)
    const int SMO = 3 * (TILE_B + BT3);    // 56832 (mode 3)

    static cudaStream_t s2 = nullptr;
    static cudaEvent_t evR = nullptr, evJ = nullptr;
    if (!s2) {
        cudaFuncSetAttribute(mma_gemm<0>, cudaFuncAttributeMaxDynamicSharedMemorySize, SM0);
        cudaFuncSetAttribute(mma_gemm<1>, cudaFuncAttributeMaxDynamicSharedMemorySize, SM2);
        cudaFuncSetAttribute(mma_gemm<2>, cudaFuncAttributeMaxDynamicSharedMemorySize, SM2);
        cudaFuncSetAttribute(mma_gemm<3>, cudaFuncAttributeMaxDynamicSharedMemorySize, SMO);
        cudaStreamCreateWithFlags(&s2, cudaStreamNonBlocking);
        cudaEventCreateWithFlags(&evR, cudaEventDisableTiming);
        cudaEventCreateWithFlags(&evJ, cudaEventDisableTiming);
    }

    // fork: qp chain on s2, vp chain on default stream
    cudaEventRecord(evR, 0);
    cudaStreamWaitEvent(s2, evR, 0);

    split_q_k <<<4096, 256, 0, s2>>>((const float4*)q);
    split_wq_k<<<1024, 256, 0, s2>>>((const float4*)Wq);
    mma_gemm<0><<<dim3(8, 32), 256, SM0, s2>>>(nullptr, bq, nullptr, nullptr);
    cudaEventRecord(evJ, s2);

    prep_kernel<<<1, 128>>>(conv_w, conv_b, Wloc);
    split_v_k <<<65536, 256>>>((const float4*)v);
    split_wv_k<<<1024,  256>>>((const float4*)Wv);
    mma_gemm<1><<<dim3(8, 512), 256, SM2>>>(nullptr, bias, last_attn, nullptr);

    // join: score needs qp (s2) and vp (default)
    cudaStreamWaitEvent(0, evJ, 0);
    mma_gemm<2><<<dim3(16, 256), 256, SM2>>>(nullptr, nullptr, nullptr, nullptr);
    mma_gemm<3><<<256, 256, SMO>>>(nullptr, nullptr, nullptr, out);
}

// round 17
// speedup vs baseline: 1.1029x; 1.0440x over previous
#include <cuda_runtime.h>
#include <cuda_fp16.h>
#include <cstdint>

#define DI __device__ __forceinline__

static const int QL  = 128;
static const int VL  = 2048;
static const int HID = 1024;

// ---------------------------------------------------------------------------
// Scratch (device globals; no runtime allocation allowed). fp16 operands.
// ---------------------------------------------------------------------------
__device__ uint16_t s_q_h[4194304], s_q_l[4194304];     // split q (2-pass A)
__device__ uint16_t s_v_h[67108864];                    // v hi (1-pass A)
__device__ uint16_t s_Wq_h[1048576];                    // Wq hi
__device__ uint16_t s_Wv_h[1048576];                    // Wv hi
__device__ uint16_t g_qh_h[4194304];                    // qp result [n][q][d]
__device__ uint16_t g_vh_h[67108864];                   // vp result [n][v][d]
__device__ float g_A0[128], g_A1[128], g_A2[128], g_Cc[128];
__device__ float g_mp[524288], g_lp[524288];            // softmax partials [n][16][128]

// ---------------------------------------------------------------------------
DI uint32_t smem_u32(const void* p) {
    uint32_t a;
    asm("{ .reg .u64 t; cvta.to.shared.u64 t, %1; cvt.u32.u64 %0, t; }" : "=r"(a) : "l"(p));
    return a;
}

DI uint32_t sp2h(float a, float b, uint32_t& lo) {
    __half2 h = __floats2half2_rn(a, b);
    float2 f = __half22float2(h);
    __half2 l = __floats2half2_rn(a - f.x, b - f.y);
    lo = *(uint32_t*)&l;
    return *(uint32_t*)&h;
}
DI uint32_t pk2h(float a, float b) {
    __half2 h = __floats2half2_rn(a, b);
    return *(uint32_t*)&h;
}

DI void ldm4(uint32_t* r, uint32_t a) {
    asm volatile("ldmatrix.sync.aligned.m8n8.x4.shared.b16 {%0,%1,%2,%3}, [%4];"
        : "=r"(r[0]), "=r"(r[1]), "=r"(r[2]), "=r"(r[3]) : "r"(a));
}
DI void ldm4t(uint32_t* r, uint32_t a) {
    asm volatile("ldmatrix.sync.aligned.m8n8.x4.trans.shared.b16 {%0,%1,%2,%3}, [%4];"
        : "=r"(r[0]), "=r"(r[1]), "=r"(r[2]), "=r"(r[3]) : "r"(a));
}

DI void mma16816(float* d, const uint32_t* a, uint32_t b0, uint32_t b1) {
    asm volatile("mma.sync.aligned.m16n8k16.row.col.f32.f16.f16.f32 "
        "{%0,%1,%2,%3},{%4,%5,%6,%7},{%8,%9},{%0,%1,%2,%3};"
        : "+f"(d[0]), "+f"(d[1]), "+f"(d[2]), "+f"(d[3])
        : "r"(a[0]), "r"(a[1]), "r"(a[2]), "r"(a[3]), "r"(b0), "r"(b1));
}

DI void cp16(uint32_t dst, const void* src) {
    asm volatile("cp.async.cg.shared.global [%0], [%1], 16;" :: "r"(dst), "l"(src));
}
#define CP_COMMIT() asm volatile("cp.async.commit_group;" ::: "memory")
#define CP_WAIT2()  asm volatile("cp.async.wait_group 2;"  ::: "memory")
#define CP_WAIT3()  asm volatile("cp.async.wait_group 3;"  ::: "memory")

static const int TILE_B = 10240;
static const int BT3    = 8704;          // MODE 3 B tile: 32 rows x 272B

// ---------------------------------------------------------------------------
// Unified GEMM, 128x128 tile, 2 CTAs/SM.
// MODE 0: qp = q@Wq^T + bq       -> g_qh_h       grid(8, 32)  3-stage, 2-pass A
// MODE 1: vp = v@Wv^T + bias+loc -> g_vh_h       grid(8, 512) 4-stage, 1-pass A
// MODE 2: score: e=exp(s-m_tile) -> attn + (m,l) grid(16,256) 4-stage, 1-pass A
// MODE 3: out = P@vh, P=e*corr   -> out; attn=P  grid(256)    3-stage, reg A; B trans
// ---------------------------------------------------------------------------
template <int MODE>
__global__ void __launch_bounds__(256, 2)
mma_gemm(const float* __restrict__ Ain, const float* __restrict__ biasv,
         const float* __restrict__ la, float* __restrict__ dsto)
{
    extern __shared__ char sm[];
    const uint32_t smb = smem_u32(sm);
    const int t = threadIdx.x, lane = t & 31, w = t >> 5;
    const int wm0 = (w & 3) * 32, wn0 = (w >> 2) * 64;

    constexpr int  K    = (MODE < 2) ? HID : (MODE == 2 ? 128 : VL);
    constexpr int  NC   = K / 32;
    constexpr int  NPA  = (MODE == 0) ? 2 : 1;
    constexpr int  NT   = (MODE == 0) ? 3 : 2;
    constexpr int  NST  = (MODE == 1 || MODE == 2) ? 4 : 3;   // pipeline depth
    constexpr int  BUF  = (MODE == 3) ? (TILE_B + BT3) : NT * TILE_B;
    constexpr uint32_t BOFF = (MODE == 3) ? (uint32_t)TILE_B
                                          : (uint32_t)(NT - 1) * TILE_B;
    constexpr bool REGA = (MODE == 3);
    constexpr int  LD   = (MODE < 2) ? HID : 128;

    const uint16_t *Ah = nullptr, *Al = nullptr, *Bh = nullptr;
    const float* Afp = nullptr;
    float* attw = nullptr;
    const float* mpRow = nullptr;
    float m_st = 0.f, li_st = 0.f;
    if (MODE == 0) {
        size_t ao = (size_t)blockIdx.y * 128 * HID, bo = (size_t)blockIdx.x * 128 * HID;
        Ah = s_q_h + ao; Al = s_q_l + ao; Bh = s_Wq_h + bo;
    } else if (MODE == 1) {
        size_t ao = (size_t)blockIdx.y * 128 * HID, bo = (size_t)blockIdx.x * 128 * HID;
        Ah = s_v_h + ao; Bh = s_Wv_h + bo;
    } else if (MODE == 2) {
        Ah = g_qh_h + (size_t)blockIdx.y * QL * 128;
        Bh = g_vh_h + (size_t)blockIdx.y * VL * 128 + (size_t)blockIdx.x * 128 * 128;
    } else {
        Afp  = Ain + (size_t)blockIdx.x * QL * VL;
        attw = (float*)Ain + (size_t)blockIdx.x * QL * VL;
        Bh   = g_vh_h + (size_t)blockIdx.x * VL * 128;
        const int myrow = t >> 1;
        mpRow = g_mp + (size_t)blockIdx.x * 2048 + myrow;
        const float* lp = g_lp + (size_t)blockIdx.x * 2048 + myrow;
        float m = -1e30f;
#pragma unroll
        for (int i = 0; i < 16; i++) m = fmaxf(m, mpRow[i * 128]);
        float l = 0.f;
#pragma unroll
        for (int i = 0; i < 16; i++) l += lp[i * 128] * __expf(mpRow[i * 128] - m);
        m_st = m; li_st = 1.0f / l;
    }

    float acc[2][8][4];
#pragma unroll
    for (int i = 0; i < 2; i++)
#pragma unroll
        for (int j = 0; j < 8; j++)
#pragma unroll
            for (int k = 0; k < 4; k++) acc[i][j][k] = 0.f;

    // ---- cp.async loaders ----
    auto cp_chunk = [&](int buf, int c) {
        uint32_t sb = smb + buf * BUF;
        if (MODE == 3) {
#pragma unroll
            for (int i = 0; i < 2; i++) {
                int idx = t + 256 * i;
                int r = idx >> 4, s = idx & 15;
                cp16(sb + BOFF + r * 272 + s * 16, Bh + (size_t)(c * 32 + r) * 128 + s * 8);
            }
        } else {
#pragma unroll
            for (int i = 0; i < NT * 2; i++) {
                int idx = t + 256 * i;
                int tile = idx >> 9, r = (idx >> 2) & 127, s = idx & 3;
                const uint16_t* base; uint32_t doff;
                if (NT == 2) { base = tile ? Bh : Ah; doff = tile ? TILE_B : 0u; }
                else {
                    base = (tile == 0) ? Ah : (tile == 1) ? Al : Bh;
                    doff = (uint32_t)tile * TILE_B;
                }
                cp16(sb + doff + r * 80 + s * 16, base + (size_t)r * LD + c * 32 + s * 8);
            }
        }
    };

    auto compute = [&](uint32_t sbuf) {
#pragma unroll
        for (int ks = 0; ks < 2; ks++) {
            const uint32_t rowsel = (uint32_t)(lane & 15) * 80
                                  + (uint32_t)((lane >> 4) + ks * 2) * 16;
            uint32_t aH[2][4], bH[4][4];
#pragma unroll
            for (int mt = 0; mt < 2; mt++)
                ldm4(aH[mt], sbuf + (uint32_t)(wm0 + mt * 16) * 80 + rowsel);
            if (MODE == 3) {
                const uint32_t rsel = (uint32_t)((lane & 7) + ((lane >> 4) << 3) + ks * 16) * 272
                                    + (uint32_t)(((lane >> 3) & 1) << 4);
#pragma unroll
                for (int g = 0; g < 4; g++)
                    ldm4t(bH[g], sbuf + BOFF + rsel + (uint32_t)(wn0 + g * 16) * 2);
            } else {
#pragma unroll
                for (int g = 0; g < 4; g++)
                    ldm4(bH[g], sbuf + BOFF + (uint32_t)(wn0 + g * 16) * 80 + rowsel);
            }
#pragma unroll
            for (int mt = 0; mt < 2; mt++)
#pragma unroll
                for (int g = 0; g < 4; g++) {
                    mma16816(acc[mt][2 * g],     aH[mt], bH[g][0], bH[g][2]);
                    mma16816(acc[mt][2 * g + 1], aH[mt], bH[g][1], bH[g][3]);
                }
            if (NPA == 2) {
#pragma unroll
                for (int mt = 0; mt < 2; mt++)
                    ldm4(aH[mt], sbuf + TILE_B + (uint32_t)(wm0 + mt * 16) * 80 + rowsel);
#pragma unroll
                for (int mt = 0; mt < 2; mt++)
#pragma unroll
                    for (int g = 0; g < 4; g++) {
                        mma16816(acc[mt][2 * g],     aH[mt], bH[g][0], bH[g][2]);
                        mma16816(acc[mt][2 * g + 1], aH[mt], bH[g][1], bH[g][3]);
                    }
            }
        }
    };

    // ---- MODE 3 register A path: e -> P = e*corr, write attn, fp16 to smem ----
    float4 arg[4];
    const float* apA = REGA ? Afp + (size_t)(t >> 1) * VL + (t & 1) * 16 : nullptr;
    float* awA = REGA ? attw + (size_t)(t >> 1) * VL + (t & 1) * 16 : nullptr;
    const uint32_t aoff = (t >> 1) * 80 + (t & 1) * 32;

    auto LD_A = [&](int c) {
#pragma unroll
        for (int j = 0; j < 4; j++) arg[j] = *(const float4*)(apA + (size_t)c * 32 + j * 4);
    };
    auto STS_A = [&](int buf, int ch) {
        char* bb = sm + buf * BUF;
        float cr = __expf(mpRow[(ch >> 2) * 128] - m_st) * li_st;
        float* aw = awA + (size_t)ch * 32;
        float4 P[4];
#pragma unroll
        for (int j = 0; j < 4; j++) {
            P[j].x = arg[j].x * cr; P[j].y = arg[j].y * cr;
            P[j].z = arg[j].z * cr; P[j].w = arg[j].w * cr;
            *(float4*)(aw + j * 4) = P[j];
        }
        uint4 H;
        H.x = pk2h(P[0].x, P[0].y); H.y = pk2h(P[0].z, P[0].w);
        H.z = pk2h(P[1].x, P[1].y); H.w = pk2h(P[1].z, P[1].w);
        *(uint4*)(bb + aoff) = H;
        H.x = pk2h(P[2].x, P[2].y); H.y = pk2h(P[2].z, P[2].w);
        H.z = pk2h(P[3].x, P[3].y); H.w = pk2h(P[3].z, P[3].w);
        *(uint4*)(bb + aoff + 16) = H;
    };

    // ---- prologue: fill NST stages ----
    if (REGA) {
        LD_A(0); STS_A(0, 0);
        LD_A(1); STS_A(1, 1);
        LD_A(2); STS_A(2, 2);
        LD_A(3);
    }
#pragma unroll
    for (int i = 0; i < NST; i++) {
        if (i < NC) cp_chunk(i, i);
        CP_COMMIT();
    }

    int buf = 0;
    for (int c = 0; c < NC; c++) {
        if (NST == 4) CP_WAIT3(); else CP_WAIT2();
        __syncthreads();
        compute(smb + buf * BUF);
        __syncthreads();
        if (c + NST < NC) {
            if (REGA) STS_A(buf, c + NST);
            cp_chunk(buf, c + NST);
        } else if (REGA && c + NST == NC) {
            // no more B chunks, but no STS either (all P staged)
        }
        CP_COMMIT();
        if (REGA && c + NST + 1 < NC + 1 && c + 4 < NC) LD_A(c + 4);
        buf = (buf == NST - 1) ? 0 : buf + 1;
    }

    // ------------------------- epilogues -------------------------
    if (MODE == 2) {
        // attn <- e = exp(s*sc - m_tile); partials (m_tile, l_tile) -> g_mp/g_lp
        float* pm = (float*)(sm + 34048);
        float* mM = pm + 256;
        float* pl = mM + 128;
        const float sc = 0.08838834764831845f;
#pragma unroll
        for (int mt = 0; mt < 2; mt++)
#pragma unroll
            for (int h2 = 0; h2 < 2; h2++) {
                const int row = wm0 + mt * 16 + (lane >> 2) + h2 * 8;
                float mx = -1e30f;
#pragma unroll
                for (int nt = 0; nt < 8; nt++)
                    mx = fmaxf(mx, fmaxf(acc[mt][nt][2 * h2], acc[mt][nt][2 * h2 + 1]));
                mx *= sc;
                mx = fmaxf(mx, __shfl_xor_sync(~0u, mx, 1));
                mx = fmaxf(mx, __shfl_xor_sync(~0u, mx, 2));
                if ((lane & 3) == 0) pm[(w >> 2) * 128 + row] = mx;
            }
        __syncthreads();
        if (t < 128) mM[t] = fmaxf(pm[t], pm[128 + t]);
        __syncthreads();
#pragma unroll
        for (int mt = 0; mt < 2; mt++)
#pragma unroll
            for (int h2 = 0; h2 < 2; h2++) {
                const int row = wm0 + mt * 16 + (lane >> 2) + h2 * 8;
                const float mm = mM[row];
                float* ad = dsto + ((size_t)blockIdx.y * QL + row) * VL + blockIdx.x * 128;
                float l = 0.f;
#pragma unroll
                for (int nt = 0; nt < 8; nt++) {
                    const int col = wn0 + nt * 8 + 2 * (lane & 3);
                    float e0 = __expf(acc[mt][nt][2 * h2]     * sc - mm);
                    float e1 = __expf(acc[mt][nt][2 * h2 + 1] * sc - mm);
                    *(float2*)(ad + col) = make_float2(e0, e1);
                    l += e0 + e1;
                }
                l += __shfl_xor_sync(~0u, l, 1);
                l += __shfl_xor_sync(~0u, l, 2);
                if ((lane & 3) == 0) pl[(w >> 2) * 128 + row] = l;
            }
        __syncthreads();
        if (t < 128) {
            size_t o = ((size_t)blockIdx.y * 16 + blockIdx.x) * 128 + t;
            g_mp[o] = mM[t];
            g_lp[o] = pl[t] + pl[128 + t];
        }
        return;
    }

    float* vec = (float*)(sm + 34048);
    if (MODE == 0) {
        if (t < 128) vec[t] = biasv[blockIdx.x * 128 + t];
    }
    if (MODE == 1) {
        if (t < 128) {
            vec[t]       = biasv[blockIdx.x * 128 + t] + g_Cc[t];
            vec[128 + t] = g_A0[t];
            vec[256 + t] = g_A1[t];
            vec[384 + t] = g_A2[t];
        }
        const int b = blockIdx.y >> 4, h = blockIdx.x;
        const int vpos0 = (blockIdx.y & 15) * 128;
        const float* lar = la + (size_t)(b * 8 + h) * VL;
        if (t < 130) {
            int g = vpos0 - 1 + t;
            vec[512 + t] = (g >= 0 && g < VL) ? lar[g] : 0.f;
        }
    }
    __syncthreads();

#pragma unroll
    for (int mt = 0; mt < 2; mt++) {
#pragma unroll
        for (int h2 = 0; h2 < 2; h2++) {
            const int row = wm0 + mt * 16 + (lane >> 2) + h2 * 8;
            size_t obase = 0;
            float* dst = nullptr;
            float lm1 = 0.f, l0 = 0.f, lp1 = 0.f;
            if (MODE == 0) {
                obase = (((size_t)(blockIdx.x * 32 + blockIdx.y)) * QL + row) * 128;
            } else if (MODE == 1) {
                int b = blockIdx.y >> 4, h = blockIdx.x;
                int vpos0 = (blockIdx.y & 15) * 128;
                lm1 = vec[512 + row]; l0 = vec[513 + row]; lp1 = vec[514 + row];
                obase = (((size_t)(h * 32 + b)) * VL + vpos0 + row) * 128;
            } else {
                int h = blockIdx.x >> 5, b = blockIdx.x & 31;
                dst = dsto + ((size_t)(b * QL + row)) * HID + h * 128;
            }
#pragma unroll
            for (int nt = 0; nt < 8; nt++) {
                const int col = wn0 + nt * 8 + 2 * (lane & 3);
                float x = acc[mt][nt][2 * h2];
                float y = acc[mt][nt][2 * h2 + 1];
                if (MODE == 0) {
                    x += vec[col]; y += vec[col + 1];
                    *(uint32_t*)&g_qh_h[obase + col] = pk2h(x, y);
                } else if (MODE == 1) {
                    x += vec[col]     + vec[128 + col]     * lm1 + vec[256 + col]     * l0 + vec[384 + col]     * lp1;
                    y += vec[col + 1] + vec[128 + col + 1] * lm1 + vec[256 + col + 1] * l0 + vec[384 + col + 1] * lp1;
                    *(uint32_t*)&g_vh_h[obase + col] = pk2h(x, y);
                } else {
                    *(float2*)(dst + col) = make_float2(x, y);
                }
            }
        }
    }
}

// ---------------------------------------------------------------------------
// fp32 -> fp16 splits
// ---------------------------------------------------------------------------
DI void split2_body(const float4* __restrict__ in, uint16_t* oh, uint16_t* ol, int n4) {
    int i = blockIdx.x * 256 + threadIdx.x;
    if (i >= n4) return;
    float4 x = in[i];
    uint32_t l0, l1;
    uint32_t h0 = sp2h(x.x, x.y, l0), h1 = sp2h(x.z, x.w, l1);
    uint2 H; H.x = h0; H.y = h1;
    *(uint2*)&oh[(size_t)i * 4] = H;
    uint2 L; L.x = l0; L.y = l1;
    *(uint2*)&ol[(size_t)i * 4] = L;
}
DI void split1_body(const float4* __restrict__ in, uint16_t* oh, int n4) {
    int i = blockIdx.x * 256 + threadIdx.x;
    if (i >= n4) return;
    float4 x = in[i];
    uint2 H;
    H.x = pk2h(x.x, x.y); H.y = pk2h(x.z, x.w);
    *(uint2*)&oh[(size_t)i * 4] = H;
}
__global__ void split_q_k(const float4* in)  { split2_body(in, s_q_h, s_q_l, 1048576); }
__global__ void split_v_k(const float4* in)  { split1_body(in, s_v_h, 16777216); }
__global__ void split_wq_k(const float4* in) { split1_body(in, s_Wq_h, 262144); }
__global__ void split_wv_k(const float4* in) { split1_body(in, s_Wv_h, 262144); }

// ---------------------------------------------------------------------------
__global__ void prep_kernel(const float* __restrict__ conv_w,
                            const float* __restrict__ conv_b,
                            const float* __restrict__ Wloc)
{
    int d = threadIdx.x;
    float a0 = 0.f, a1 = 0.f, a2 = 0.f, c = 0.f;
#pragma unroll
    for (int cc = 0; cc < 10; cc++) {
        float wl = Wloc[d * 10 + cc];
        a0 += wl * conv_w[cc * 3 + 0];
        a1 += wl * conv_w[cc * 3 + 1];
        a2 += wl * conv_w[cc * 3 + 2];
        c  += wl * conv_b[cc];
    }
    g_A0[d] = a0; g_A1[d] = a1; g_A2[d] = a2; g_Cc[d] = c;
}

// ---------------------------------------------------------------------------
extern "C" void kernel_launch(void* const* d_in, const int* in_sizes, int n_in,
                              void* d_out, int out_size)
{
    const float* q         = (const float*)d_in[0];
    const float* v         = (const float*)d_in[1];
    const float* last_attn = (const float*)d_in[2];
    const float* conv_w    = (const float*)d_in[3];
    const float* conv_b    = (const float*)d_in[4];
    const float* Wq        = (const float*)d_in[5];
    const float* bq        = (const float*)d_in[6];
    const float* Wv        = (const float*)d_in[7];
    const float* Wloc      = (const float*)d_in[8];
    const float* bias      = (const float*)d_in[9];

    float* out  = (float*)d_out;
    float* attn = out + 4194304;

    const int SM0 = 3 * 3 * TILE_B;        // 92160 (mode 0, 3-stage)
    const int SM1 = 4 * 2 * TILE_B;        // 81920 (modes 1/2, 4-stage)
    const int SMO = 3 * (TILE_B + BT3);    // 56832 (mode 3, 3-stage)

    static cudaStream_t s2 = nullptr;
    static cudaEvent_t evR = nullptr, evJ = nullptr;
    if (!s2) {
        cudaFuncSetAttribute(mma_gemm<0>, cudaFuncAttributeMaxDynamicSharedMemorySize, SM0);
        cudaFuncSetAttribute(mma_gemm<1>, cudaFuncAttributeMaxDynamicSharedMemorySize, SM1);
        cudaFuncSetAttribute(mma_gemm<2>, cudaFuncAttributeMaxDynamicSharedMemorySize, SM1);
        cudaFuncSetAttribute(mma_gemm<3>, cudaFuncAttributeMaxDynamicSharedMemorySize, SMO);
        cudaStreamCreateWithFlags(&s2, cudaStreamNonBlocking);
        cudaEventCreateWithFlags(&evR, cudaEventDisableTiming);
        cudaEventCreateWithFlags(&evJ, cudaEventDisableTiming);
    }

    // fork: qp chain on s2, vp chain on default stream
    cudaEventRecord(evR, 0);
    cudaStreamWaitEvent(s2, evR, 0);

    split_q_k <<<4096, 256, 0, s2>>>((const float4*)q);
    split_wq_k<<<1024, 256, 0, s2>>>((const float4*)Wq);
    mma_gemm<0><<<dim3(8, 32), 256, SM0, s2>>>(nullptr, bq, nullptr, nullptr);
    cudaEventRecord(evJ, s2);

    prep_kernel<<<1, 128>>>(conv_w, conv_b, Wloc);
    split_v_k <<<65536, 256>>>((const float4*)v);
    split_wv_k<<<1024,  256>>>((const float4*)Wv);
    mma_gemm<1><<<dim3(8, 512), 256, SM1>>>(nullptr, bias, last_attn, nullptr);

    // join: score needs qp (s2) and vp (default)
    cudaStreamWaitEvent(0, evJ, 0);
    mma_gemm<2><<<dim3(16, 256), 256, SM1>>>(nullptr, nullptr, nullptr, attn);
    mma_gemm<3><<<256, 256, SMO>>>(attn, nullptr, nullptr, out);
}